// round 7
// baseline (speedup 1.0000x reference)
#include <cuda_runtime.h>
#include <cstdint>
#include <math.h>

// Problem constants (fixed by setup_inputs)
#define VOCAB   512
#define EMB     256
#define HID     64
#define N_POS   (32 * 4096)   // B * L = 131072
#define N_STEPS 5
#define DT_F32  0.01f         // float32(T_HORIZON / steps)
#define TINY_F  1.17549435082228750797e-38f  // finfo(float32).tiny

// -------- scratch: __device__ globals only --------
__device__ float g_H[VOCAB * HID];        // relu(emb @ W1 + b1)
__device__ float g_T[VOCAB * VOCAB];      // intensity table
__device__ float g_pub[VOCAB];            // per-state accept upper bound (+margin)
__device__ int   g_state[2][N_POS];       // ping-pong state buffers
__device__ int   g_queue[N_POS];          // compacted maybe-accept positions
__device__ int   g_cnt[N_STEPS];          // queue counts per step
__device__ int   g_xmode;                 // 0:A-int 1:A-f32 2:B-int 3:B-f32

// ---- correctly-rounded f32 transcendentals (match glibc scalar expf/logf) ----
__device__ __forceinline__ float cr_logf(float x) {
    return (float)log((double)x);
}
__device__ __forceinline__ float cr_expf(float x) {
    return (float)exp((double)x);
}

// ===================== threefry-2x32 (exact JAX schedule) =====================
__device__ __forceinline__ void tf_round(uint32_t& x0, uint32_t& x1, int r) {
    x0 += x1;
    x1 = __funnelshift_l(x1, x1, r);  // rotl32
    x1 ^= x0;
}

__device__ __forceinline__ uint2 tf2x32(uint32_t k0, uint32_t k1,
                                        uint32_t x0, uint32_t x1) {
    uint32_t ks2 = k0 ^ k1 ^ 0x1BD11BDAu;
    x0 += k0; x1 += k1;
    tf_round(x0,x1,13); tf_round(x0,x1,15); tf_round(x0,x1,26); tf_round(x0,x1, 6);
    x0 += k1;  x1 += ks2 + 1u;
    tf_round(x0,x1,17); tf_round(x0,x1,29); tf_round(x0,x1,16); tf_round(x0,x1,24);
    x0 += ks2; x1 += k0 + 2u;
    tf_round(x0,x1,13); tf_round(x0,x1,15); tf_round(x0,x1,26); tf_round(x0,x1, 6);
    x0 += k0;  x1 += k1 + 3u;
    tf_round(x0,x1,17); tf_round(x0,x1,29); tf_round(x0,x1,16); tf_round(x0,x1,24);
    x0 += k1;  x1 += ks2 + 4u;
    tf_round(x0,x1,13); tf_round(x0,x1,15); tf_round(x0,x1,26); tf_round(x0,x1, 6);
    x0 += ks2; x1 += k0 + 5u;
    return make_uint2(x0, x1);
}

static inline uint32_t h_rotl(uint32_t x, int r) { return (x << r) | (x >> (32 - r)); }
static void h_tf2x32(uint32_t k0, uint32_t k1, uint32_t x0, uint32_t x1,
                     uint32_t& o0, uint32_t& o1) {
    uint32_t ks2 = k0 ^ k1 ^ 0x1BD11BDAu;
    static const int R[20] = {13,15,26,6, 17,29,16,24, 13,15,26,6, 17,29,16,24, 13,15,26,6};
    x0 += k0; x1 += k1;
    const uint32_t ks[3] = {k0, k1, ks2};
    for (int g = 0; g < 5; g++) {
        for (int j = 0; j < 4; j++) {
            int r = R[g * 4 + j];
            x0 += x1; x1 = h_rotl(x1, r); x1 ^= x0;
        }
        x0 += ks[(g + 1) % 3];
        x1 += ks[(g + 2) % 3] + (uint32_t)(g + 1);
    }
    o0 = x0; o1 = x1;
}

// partitionable random_bits(32): counter (hi=0, lo=idx), out = o0 ^ o1
__device__ __forceinline__ uint32_t jax_bits32(uint32_t k0, uint32_t k1, uint32_t idx) {
    uint2 r = tf2x32(k0, k1, 0u, idx);
    return r.x ^ r.y;
}

__device__ __forceinline__ float bits_to_u01(uint32_t bits) {
    return __uint_as_float((bits >> 9) | 0x3f800000u) - 1.0f;
}

// ===================== setup / io kernels =====================
__global__ void k_reset() {
    if (threadIdx.x < N_STEPS) g_cnt[threadIdx.x] = 0;
}

// DIAGNOSTIC fallback: mapping failed -> constant 1000.0f (rel_err ~ 2.3)
__global__ void k_fallback(float* __restrict__ out) {
    int i = blockIdx.x * blockDim.x + threadIdx.x;
    if (i < N_POS) out[i] = 1000.0f;
}

// Classify the ambiguous 131072-element pair (x vs emb_table).
__global__ void k_detect(const uint32_t* __restrict__ A,
                         const uint32_t* __restrict__ B) {
    __shared__ int aInt, aF32, bInt;
    if (threadIdx.x == 0) { aInt = 1; aF32 = 1; bInt = 1; }
    __syncthreads();
    int laI = 1, laF = 1, lbI = 1;
    for (int i = threadIdx.x; i < N_POS; i += blockDim.x) {
        uint32_t wa = A[i], wb = B[i];
        if (wa >= 512u) laI = 0;
        if (!(wa == 0u || (wa >= 0x3f800000u && wa <= 0x43ff8000u))) laF = 0;
        if (wb >= 512u) lbI = 0;
    }
    if (!laI) atomicAnd(&aInt, 0);
    if (!laF) atomicAnd(&aF32, 0);
    if (!lbI) atomicAnd(&bInt, 0);
    __syncthreads();
    if (threadIdx.x == 0) {
        int mode;
        if      (aInt) mode = 0;     // A is x (int32)
        else if (aF32) mode = 1;     // A is x (float32)
        else if (bInt) mode = 2;     // B is x (int32)
        else           mode = 3;     // B is x (float32)
        g_xmode = mode;
    }
}

__global__ void k_canon(const uint32_t* __restrict__ A, const uint32_t* __restrict__ B) {
    int i = blockIdx.x * blockDim.x + threadIdx.x;
    if (i >= N_POS) return;
    int mode = g_xmode;
    const uint32_t* xp = (mode < 2) ? A : B;
    uint32_t w = xp[i];
    int s = (mode & 1) ? (int)__uint_as_float(w) : (int)w;
    g_state[0][i] = min(max(s, 0), VOCAB - 1);
}

__global__ void k_emit(float* __restrict__ out) {
    int i = blockIdx.x * blockDim.x + threadIdx.x;
    if (i >= N_POS) return;
    out[i] = (float)g_state[N_STEPS & 1][i];
}

// ===================== table kernels =====================
// Sequential-k single-accumulator fma chains: bit-identical to Eigen gebp /
// cublas SIMT sgemm accumulation for these shapes.
__global__ void k_hidden(const void* __restrict__ A, const void* __restrict__ B,
                         const float* __restrict__ W1,
                         const float* __restrict__ b1) {
    int idx = blockIdx.x * blockDim.x + threadIdx.x;   // s*HID + j
    if (idx >= VOCAB * HID) return;
    const float* emb = (const float*)((g_xmode < 2) ? B : A);  // the non-x buffer
    int s = idx >> 6;
    int j = idx & 63;
    const float* e = emb + s * EMB;
    float acc = 0.0f;
    #pragma unroll 8
    for (int k = 0; k < EMB; k++)
        acc = fmaf(e[k], W1[k * HID + j], acc);
    g_H[idx] = fmaxf(acc + b1[j], 0.0f);
}

__global__ void k_table(const float* __restrict__ W2,
                        const float* __restrict__ b2) {
    int idx = blockIdx.x * blockDim.x + threadIdx.x;   // s*VOCAB + v
    if (idx >= VOCAB * VOCAB) return;
    int s = idx >> 9;
    int v = idx & 511;
    const float* h = g_H + s * HID;
    float acc = 0.0f;
    #pragma unroll
    for (int j = 0; j < HID; j++)
        acc = fmaf(h[j], W2[j * VOCAB + v], acc);
    g_T[idx] = acc + b2[v];
}

// per-state accept upper bound: p_ub[s] = 1 - exp(-rowmax[s]*dt) + margin
__global__ void k_rowmax() {
    int w = blockIdx.x * (blockDim.x >> 5) + (threadIdx.x >> 5);
    int lane = threadIdx.x & 31;
    if (w >= VOCAB) return;
    const float* row = g_T + (w << 9);
    float m = __int_as_float(0xff800000);
    #pragma unroll
    for (int v = lane; v < VOCAB; v += 32) m = fmaxf(m, row[v]);
    #pragma unroll
    for (int off = 16; off; off >>= 1)
        m = fmaxf(m, __shfl_xor_sync(0xffffffffu, m, off));
    if (lane == 0)
        g_pub[w] = 1.0f - cr_expf(-(m * DT_F32)) + 1e-5f;
}

// ===================== step phase A: certain-reject filter =====================
__global__ void k_phaseA(int t, uint32_t k2a, uint32_t k2b) {
    int i = blockIdx.x * blockDim.x + threadIdx.x;
    if (i >= N_POS) return;
    int s = min(max(g_state[t & 1][i], 0), VOCAB - 1);
    g_state[(t + 1) & 1][i] = s;
    uint32_t b = jax_bits32(k2a, k2b, (uint32_t)i);
    float u2 = bits_to_u01(b);
    if (u2 < g_pub[s]) {
        int pos = atomicAdd(&g_cnt[t], 1);
        if (pos < N_POS) g_queue[pos] = i;
    }
}

// ===================== step phase B: exact categorical on queued positions ====
__global__ void __launch_bounds__(256)
k_phaseB(int t, uint32_t k1a, uint32_t k1b, uint32_t k2a, uint32_t k2b) {
    int gw   = blockIdx.x * (blockDim.x >> 5) + (threadIdx.x >> 5);
    int lane = threadIdx.x & 31;
    int nw   = gridDim.x * (blockDim.x >> 5);
    int qn   = min(g_cnt[t], N_POS);
    const int* xin  = g_state[t & 1];
    int*       xout = g_state[(t + 1) & 1];

    for (int q = gw; q < qn; q += nw) {
        int pos = g_queue[q];
        int s = min(max(xin[pos], 0), VOCAB - 1);
        const float* __restrict__ row = g_T + (s << 9);
        uint32_t base = ((uint32_t)pos) << 9;          // flat index in [B,L,V]

        float best = __int_as_float(0xff800000);
        int   bidx = VOCAB;

        for (int i = 0; i < 16; i++) {
            int v = (i << 5) + lane;
            uint32_t bits = jax_bits32(k1a, k1b, base + (uint32_t)v);
            float u01 = bits_to_u01(bits);
            float u = fmaxf(TINY_F, u01 + TINY_F);     // uniform(minval=tiny)
            // gumbel with float intermediates, each log correctly rounded:
            float r1 = cr_logf(u);
            float r2 = cr_logf(-r1);
            float g  = -r2;
            float cand = row[v] + g;
            if (v != s && (cand > best || (cand == best && v < bidx))) {
                best = cand; bidx = v;
            }
        }
        #pragma unroll
        for (int off = 16; off; off >>= 1) {
            float ov = __shfl_xor_sync(0xffffffffu, best, off);
            int   oi = __shfl_xor_sync(0xffffffffu, bidx, off);
            if (ov > best || (ov == best && oi < bidx)) { best = ov; bidx = oi; }
        }

        if (lane == 0) {
            float rate   = row[bidx];                  // unmasked intensity
            float accept = 1.0f - cr_expf(-(rate * DT_F32));
            uint32_t bb  = jax_bits32(k2a, k2b, (uint32_t)pos);
            float u2     = bits_to_u01(bb);
            xout[pos] = (u2 < accept) ? bidx : s;
        }
    }
}

// ===================== launch =====================
extern "C" void kernel_launch(void* const* d_in, const int* in_sizes, int n_in,
                              void* d_out, int out_size) {
    (void)out_size;
    // -------- dual-convention size mapping (elements OR bytes) --------
    bool has_e_w1=false, has_e_b1=false, has_e_w2=false, has_e_b2=false;
    bool has_b_w1=false, has_b_b1=false, has_b_w2=false, has_b_b2=false;
    for (int i = 0; i < n_in; i++) {
        int sz = in_sizes[i];
        if (sz == 16384)  has_e_w1 = true;
        if (sz == 64)     has_e_b1 = true;
        if (sz == 32768)  has_e_w2 = true;
        if (sz == 512)    has_e_b2 = true;
        if (sz == 65536)  has_b_w1 = true;
        if (sz == 256)    has_b_b1 = true;
        if (sz == 131072) has_b_w2 = true;
        if (sz == 2048)   has_b_b2 = true;
    }
    bool elems_mode = has_e_w1 && has_e_b1 && has_e_w2 && has_e_b2;
    bool bytes_mode = !elems_mode && has_b_w1 && has_b_b1 && has_b_w2 && has_b_b2;

    const float *W1 = nullptr, *b1 = nullptr, *W2 = nullptr, *b2 = nullptr;
    const void  *cand[2] = { nullptr, nullptr };
    int ncand = 0;

    int s_w1 = elems_mode ? 16384  : 65536;
    int s_b1 = elems_mode ? 64     : 256;
    int s_w2 = elems_mode ? 32768  : 131072;
    int s_b2 = elems_mode ? 512    : 2048;
    int s_xe = elems_mode ? 131072 : 524288;

    if (elems_mode || bytes_mode) {
        for (int i = 0; i < n_in; i++) {
            int sz = in_sizes[i];
            if      (sz == s_w1) W1 = (const float*)d_in[i];
            else if (sz == s_b1) b1 = (const float*)d_in[i];
            else if (sz == s_w2) W2 = (const float*)d_in[i];
            else if (sz == s_b2) b2 = (const float*)d_in[i];
            else if (sz == s_xe) { if (ncand < 2) cand[ncand++] = d_in[i]; }
        }
    }

    bool ok = (elems_mode || bytes_mode) && W1 && b1 && W2 && b2 && ncand == 2;
    if (!ok) {
        k_fallback<<<(N_POS + 255) / 256, 256>>>((float*)d_out);
        return;
    }
    const void *bufA = cand[0], *bufB = cand[1];

    // -------- per-step keys (jax.random.key(42), partitionable fold-like) -----
    uint32_t k1a[N_STEPS], k1b[N_STEPS], k2a[N_STEPS], k2b[N_STEPS];
    for (int i = 0; i < N_STEPS; i++) {
        uint32_t sk0, sk1;
        h_tf2x32(0u, 42u, 0u, (uint32_t)i, sk0, sk1);
        h_tf2x32(sk0, sk1, 0u, 0u, k1a[i], k1b[i]);
        h_tf2x32(sk0, sk1, 0u, 1u, k2a[i], k2b[i]);
    }

    k_reset <<<1, 32>>>();
    k_detect<<<1, 1024>>>((const uint32_t*)bufA, (const uint32_t*)bufB);
    k_canon <<<(N_POS + 255) / 256, 256>>>((const uint32_t*)bufA, (const uint32_t*)bufB);

    k_hidden<<<(VOCAB * HID + 255) / 256, 256>>>(bufA, bufB, W1, b1);
    k_table <<<(VOCAB * VOCAB + 255) / 256, 256>>>(W2, b2);
    k_rowmax<<<(VOCAB * 32 + 255) / 256, 256>>>();

    for (int t = 0; t < N_STEPS; t++) {
        k_phaseA<<<(N_POS + 255) / 256, 256>>>(t, k2a[t], k2b[t]);
        k_phaseB<<<256, 256>>>(t, k1a[t], k1b[t], k2a[t], k2b[t]);
    }

    k_emit<<<(N_POS + 255) / 256, 256>>>((float*)d_out);
}

// round 8
// speedup vs baseline: 6.9153x; 6.9153x over previous
#include <cuda_runtime.h>
#include <cstdint>
#include <math.h>

// Problem constants (fixed by setup_inputs)
#define VOCAB   512
#define EMB     256
#define HID     64
#define N_POS   (32 * 4096)   // B * L = 131072
#define N_STEPS 5
#define DT_F32  0.01f         // float32(T_HORIZON / steps)
#define TINY_F  1.17549435082228750797e-38f  // finfo(float32).tiny
#define EPS2    1e-3f         // fast/exact gumbel decision margin (err bound ~3e-6)
#define NEG_INF __int_as_float(0xff800000)

// -------- scratch: __device__ globals only --------
__device__ float    g_H[VOCAB * HID];     // relu(emb @ W1 + b1)
__device__ float    g_T[VOCAB * VOCAB];   // intensity table
__device__ uint32_t g_thr[VOCAB * VOCAB]; // accept threshold in bits-space
__device__ uint32_t g_pubm[VOCAB];        // max_{v!=s} g_thr[s][v] (tight reject bound)
__device__ int      g_state[2][N_POS];    // ping-pong state buffers
__device__ int      g_queue[N_POS];       // compacted maybe-accept positions
__device__ int      g_cnt[N_STEPS];       // queue counts per step
__device__ int      g_fAInt, g_fAF32, g_fBInt;  // detect flags

// mode: 0 = A is x(int32), 1 = A is x(f32), 2 = B is x(int32), 3 = B is x(f32)
__device__ __forceinline__ int get_xmode() {
    if (g_fAInt) return 0;
    if (g_fAF32) return 1;
    if (g_fBInt) return 2;
    return 3;
}

// ===================== threefry-2x32 (exact JAX schedule) =====================
__device__ __forceinline__ void tf_round(uint32_t& x0, uint32_t& x1, int r) {
    x0 += x1;
    x1 = __funnelshift_l(x1, x1, r);
    x1 ^= x0;
}

__device__ __forceinline__ uint2 tf2x32(uint32_t k0, uint32_t k1,
                                        uint32_t x0, uint32_t x1) {
    uint32_t ks2 = k0 ^ k1 ^ 0x1BD11BDAu;
    x0 += k0; x1 += k1;
    tf_round(x0,x1,13); tf_round(x0,x1,15); tf_round(x0,x1,26); tf_round(x0,x1, 6);
    x0 += k1;  x1 += ks2 + 1u;
    tf_round(x0,x1,17); tf_round(x0,x1,29); tf_round(x0,x1,16); tf_round(x0,x1,24);
    x0 += ks2; x1 += k0 + 2u;
    tf_round(x0,x1,13); tf_round(x0,x1,15); tf_round(x0,x1,26); tf_round(x0,x1, 6);
    x0 += k0;  x1 += k1 + 3u;
    tf_round(x0,x1,17); tf_round(x0,x1,29); tf_round(x0,x1,16); tf_round(x0,x1,24);
    x0 += k1;  x1 += ks2 + 4u;
    tf_round(x0,x1,13); tf_round(x0,x1,15); tf_round(x0,x1,26); tf_round(x0,x1, 6);
    x0 += ks2; x1 += k0 + 5u;
    return make_uint2(x0, x1);
}

static inline uint32_t h_rotl(uint32_t x, int r) { return (x << r) | (x >> (32 - r)); }
static void h_tf2x32(uint32_t k0, uint32_t k1, uint32_t x0, uint32_t x1,
                     uint32_t& o0, uint32_t& o1) {
    uint32_t ks2 = k0 ^ k1 ^ 0x1BD11BDAu;
    static const int R[20] = {13,15,26,6, 17,29,16,24, 13,15,26,6, 17,29,16,24, 13,15,26,6};
    x0 += k0; x1 += k1;
    const uint32_t ks[3] = {k0, k1, ks2};
    for (int g = 0; g < 5; g++) {
        for (int j = 0; j < 4; j++) {
            int r = R[g * 4 + j];
            x0 += x1; x1 = h_rotl(x1, r); x1 ^= x0;
        }
        x0 += ks[(g + 1) % 3];
        x1 += ks[(g + 2) % 3] + (uint32_t)(g + 1);
    }
    o0 = x0; o1 = x1;
}

// partitionable random_bits(32): counter (hi=0, lo=idx), out = o0 ^ o1
__device__ __forceinline__ uint32_t jax_bits32(uint32_t k0, uint32_t k1, uint32_t idx) {
    uint2 r = tf2x32(k0, k1, 0u, idx);
    return r.x ^ r.y;
}

__device__ __forceinline__ float bits_to_u01(uint32_t bits) {
    return __uint_as_float((bits >> 9) | 0x3f800000u) - 1.0f;
}

// ===================== setup / io kernels =====================
__global__ void k_reset() {
    if (threadIdx.x < N_STEPS) g_cnt[threadIdx.x] = 0;
    if (threadIdx.x == 0) { g_fAInt = 1; g_fAF32 = 1; g_fBInt = 1; }
}

// DIAGNOSTIC fallback: mapping failed -> constant 1000.0f
__global__ void k_fallback(float* __restrict__ out) {
    int i = blockIdx.x * blockDim.x + threadIdx.x;
    if (i < N_POS) out[i] = 1000.0f;
}

// Multi-block classify of the ambiguous pair (x vs emb_table).
__global__ void k_detect(const uint32_t* __restrict__ A,
                         const uint32_t* __restrict__ B) {
    int stride = gridDim.x * blockDim.x;
    int laI = 1, laF = 1, lbI = 1;
    for (int i = blockIdx.x * blockDim.x + threadIdx.x; i < N_POS; i += stride) {
        uint32_t wa = A[i], wb = B[i];
        if (wa >= 512u) laI = 0;
        if (!(wa == 0u || (wa >= 0x3f800000u && wa <= 0x43ff8000u))) laF = 0;
        if (wb >= 512u) lbI = 0;
    }
    if (!laI) atomicAnd(&g_fAInt, 0);
    if (!laF) atomicAnd(&g_fAF32, 0);
    if (!lbI) atomicAnd(&g_fBInt, 0);
}

__global__ void k_canon(const uint32_t* __restrict__ A, const uint32_t* __restrict__ B) {
    int i = blockIdx.x * blockDim.x + threadIdx.x;
    if (i >= N_POS) return;
    int mode = get_xmode();
    const uint32_t* xp = (mode < 2) ? A : B;
    uint32_t w = xp[i];
    int s = (mode & 1) ? (int)__uint_as_float(w) : (int)w;
    g_state[0][i] = min(max(s, 0), VOCAB - 1);
}

__global__ void k_emit(float* __restrict__ out) {
    int i = blockIdx.x * blockDim.x + threadIdx.x;
    if (i >= N_POS) return;
    out[i] = (float)g_state[N_STEPS & 1][i];
}

// ===================== table kernels =====================
__global__ void k_hidden(const void* __restrict__ A, const void* __restrict__ B,
                         const float* __restrict__ W1,
                         const float* __restrict__ b1) {
    int idx = blockIdx.x * blockDim.x + threadIdx.x;   // s*HID + j
    if (idx >= VOCAB * HID) return;
    const float* emb = (const float*)((get_xmode() < 2) ? B : A);  // non-x buffer
    int s = idx >> 6;
    int j = idx & 63;
    const float4* e4 = (const float4*)(emb + s * EMB);
    float acc = 0.0f;
    #pragma unroll 16
    for (int k4 = 0; k4 < EMB / 4; k4++) {
        float4 ev = e4[k4];
        int k = k4 * 4;
        acc = fmaf(ev.x, W1[(k + 0) * HID + j], acc);
        acc = fmaf(ev.y, W1[(k + 1) * HID + j], acc);
        acc = fmaf(ev.z, W1[(k + 2) * HID + j], acc);
        acc = fmaf(ev.w, W1[(k + 3) * HID + j], acc);
    }
    g_H[idx] = fmaxf(acc + b1[j], 0.0f);
}

// intensity table + bits-space accept thresholds:
// accept iff u2 < 1 - cr_expf(-(T*dt));  u2 = m*2^-23 exact  =>  m < ceil(acc*2^23)
__global__ void k_table(const float* __restrict__ W2,
                        const float* __restrict__ b2) {
    int idx = blockIdx.x * blockDim.x + threadIdx.x;   // s*VOCAB + v
    if (idx >= VOCAB * VOCAB) return;
    int s = idx >> 9;
    int v = idx & 511;
    const float* h = g_H + s * HID;
    float acc = 0.0f;
    #pragma unroll
    for (int j = 0; j < HID; j++)
        acc = fmaf(h[j], W2[j * VOCAB + v], acc);
    float T = acc + b2[v];
    g_T[idx] = T;
    float p = T * DT_F32;
    float e = (float)exp(-(double)p);          // correctly-rounded f32 exp
    float a = 1.0f - e;                        // reference accept prob (exact chain)
    double d = ceil((double)a * 8388608.0);    // exact scaling, exact ceil
    d = fmin(fmax(d, 0.0), 8388608.0);
    g_thr[idx] = (uint32_t)d;
}

// tight per-state reject bound: pubm[s] = max_{v != s} thr[s][v]
__global__ void k_pubm() {
    int w = blockIdx.x * (blockDim.x >> 5) + (threadIdx.x >> 5);
    int lane = threadIdx.x & 31;
    if (w >= VOCAB) return;
    const uint32_t* row = g_thr + (w << 9);
    uint32_t m = 0;
    #pragma unroll
    for (int v = lane; v < VOCAB; v += 32)
        if (v != w) m = max(m, row[v]);
    #pragma unroll
    for (int off = 16; off; off >>= 1)
        m = max(m, __shfl_xor_sync(0xffffffffu, m, off));
    if (lane == 0) g_pubm[w] = m;
}

// ===================== step phase A: exact certain-reject filter ==============
__global__ void k_phaseA(int t, uint32_t k2a, uint32_t k2b) {
    int i = blockIdx.x * blockDim.x + threadIdx.x;
    if (i >= N_POS) return;
    int s = g_state[t & 1][i];
    g_state[(t + 1) & 1][i] = s;
    uint32_t m = jax_bits32(k2a, k2b, (uint32_t)i) >> 9;
    if (m < g_pubm[s]) {                      // exact: accept impossible otherwise
        int pos = atomicAdd(&g_cnt[t], 1);
        if (pos < N_POS) g_queue[pos] = i;
    }
}

// ===================== step phase B: categorical, filter-then-exact ===========
__global__ void __launch_bounds__(256)
k_phaseB(int t, uint32_t k1a, uint32_t k1b, uint32_t k2a, uint32_t k2b) {
    int gw   = blockIdx.x * (blockDim.x >> 5) + (threadIdx.x >> 5);
    int lane = threadIdx.x & 31;
    int nw   = gridDim.x * (blockDim.x >> 5);
    int qn   = min(g_cnt[t], N_POS);
    const int* xin  = g_state[t & 1];
    int*       xout = g_state[(t + 1) & 1];

    for (int q = gw; q < qn; q += nw) {
        int pos = g_queue[q];
        int s = xin[pos];
        const float* __restrict__ row = g_T + (s << 9);
        uint32_t base = ((uint32_t)pos) << 9;

        // ---- pass 1: fast gumbels (precise f32 logf, 1 ulp) ----
        float m1 = NEG_INF, m2 = NEG_INF;
        int   i1 = VOCAB;
        int   risky = 0;                       // u01 ~ 1: guard region
        for (int i = 0; i < 16; i++) {
            int v = (i << 5) + lane;
            uint32_t bits = jax_bits32(k1a, k1b, base + (uint32_t)v);
            float u01 = bits_to_u01(bits);
            float u = fmaxf(TINY_F, u01 + TINY_F);
            float g = -logf(-logf(u));
            float cand = (v == s) ? NEG_INF : (row[v] + g);
            risky |= (u01 > 0.9999f && v != s);
            if (cand > m1) { m2 = m1; m1 = cand; i1 = v; }
            else if (cand > m2) { m2 = cand; }
        }
        // warp reduce (m1,i1,m2); groups disjoint per butterfly round
        #pragma unroll
        for (int off = 16; off; off >>= 1) {
            float o1 = __shfl_xor_sync(0xffffffffu, m1, off);
            int   oi = __shfl_xor_sync(0xffffffffu, i1, off);
            float o2 = __shfl_xor_sync(0xffffffffu, m2, off);
            if (o1 > m1 || (o1 == m1 && oi < i1)) {
                m2 = fmaxf(m1, o2); m1 = o1; i1 = oi;
            } else {
                m2 = fmaxf(m2, o1);
            }
        }
        int anyRisky = __ballot_sync(0xffffffffu, risky);
        int bidx = i1;

        // ---- pass 2 (rare): exact CR recompute for near-max / risky draws ----
        if ((m1 - m2) < EPS2 || anyRisky) {
            float e1 = NEG_INF;
            int   ei = VOCAB;
            for (int i = 0; i < 16; i++) {
                int v = (i << 5) + lane;
                uint32_t bits = jax_bits32(k1a, k1b, base + (uint32_t)v);
                float u01 = bits_to_u01(bits);
                float u = fmaxf(TINY_F, u01 + TINY_F);
                float gf = -logf(-logf(u));
                float candf = row[v] + gf;
                if (v != s && (candf >= m1 - EPS2 || u01 > 0.9999f)) {
                    float r1 = (float)log((double)u);      // CR f32 log
                    float r2 = (float)log((double)(-r1));  // CR f32 log
                    float g  = -r2;
                    float cand = row[v] + g;               // exact reference chain
                    if (cand > e1) { e1 = cand; ei = v; }  // v ascending: first tie
                }
            }
            #pragma unroll
            for (int off = 16; off; off >>= 1) {
                float ov = __shfl_xor_sync(0xffffffffu, e1, off);
                int   oi = __shfl_xor_sync(0xffffffffu, ei, off);
                if (ov > e1 || (ov == e1 && oi < ei)) { e1 = ov; ei = oi; }
            }
            bidx = ei;
        }

        // ---- exact accept via integer threshold ----
        if (lane == 0) {
            uint32_t m = jax_bits32(k2a, k2b, (uint32_t)pos) >> 9;
            xout[pos] = (m < g_thr[(s << 9) | bidx]) ? bidx : s;
        }
    }
}

// ===================== launch =====================
extern "C" void kernel_launch(void* const* d_in, const int* in_sizes, int n_in,
                              void* d_out, int out_size) {
    (void)out_size;
    // -------- dual-convention size mapping (elements OR bytes) --------
    bool has_e_w1=false, has_e_b1=false, has_e_w2=false, has_e_b2=false;
    bool has_b_w1=false, has_b_b1=false, has_b_w2=false, has_b_b2=false;
    for (int i = 0; i < n_in; i++) {
        int sz = in_sizes[i];
        if (sz == 16384)  has_e_w1 = true;
        if (sz == 64)     has_e_b1 = true;
        if (sz == 32768)  has_e_w2 = true;
        if (sz == 512)    has_e_b2 = true;
        if (sz == 65536)  has_b_w1 = true;
        if (sz == 256)    has_b_b1 = true;
        if (sz == 131072) has_b_w2 = true;
        if (sz == 2048)   has_b_b2 = true;
    }
    bool elems_mode = has_e_w1 && has_e_b1 && has_e_w2 && has_e_b2;
    bool bytes_mode = !elems_mode && has_b_w1 && has_b_b1 && has_b_w2 && has_b_b2;

    const float *W1 = nullptr, *b1 = nullptr, *W2 = nullptr, *b2 = nullptr;
    const void  *cand[2] = { nullptr, nullptr };
    int ncand = 0;

    int s_w1 = elems_mode ? 16384  : 65536;
    int s_b1 = elems_mode ? 64     : 256;
    int s_w2 = elems_mode ? 32768  : 131072;
    int s_b2 = elems_mode ? 512    : 2048;
    int s_xe = elems_mode ? 131072 : 524288;

    if (elems_mode || bytes_mode) {
        for (int i = 0; i < n_in; i++) {
            int sz = in_sizes[i];
            if      (sz == s_w1) W1 = (const float*)d_in[i];
            else if (sz == s_b1) b1 = (const float*)d_in[i];
            else if (sz == s_w2) W2 = (const float*)d_in[i];
            else if (sz == s_b2) b2 = (const float*)d_in[i];
            else if (sz == s_xe) { if (ncand < 2) cand[ncand++] = d_in[i]; }
        }
    }

    bool ok = (elems_mode || bytes_mode) && W1 && b1 && W2 && b2 && ncand == 2;
    if (!ok) {
        k_fallback<<<(N_POS + 255) / 256, 256>>>((float*)d_out);
        return;
    }
    const void *bufA = cand[0], *bufB = cand[1];

    // -------- per-step keys (jax.random.key(42), partitionable fold-like) -----
    uint32_t k1a[N_STEPS], k1b[N_STEPS], k2a[N_STEPS], k2b[N_STEPS];
    for (int i = 0; i < N_STEPS; i++) {
        uint32_t sk0, sk1;
        h_tf2x32(0u, 42u, 0u, (uint32_t)i, sk0, sk1);
        h_tf2x32(sk0, sk1, 0u, 0u, k1a[i], k1b[i]);
        h_tf2x32(sk0, sk1, 0u, 1u, k2a[i], k2b[i]);
    }

    k_reset <<<1, 32>>>();
    k_detect<<<64, 256>>>((const uint32_t*)bufA, (const uint32_t*)bufB);
    k_canon <<<(N_POS + 255) / 256, 256>>>((const uint32_t*)bufA, (const uint32_t*)bufB);

    k_hidden<<<(VOCAB * HID + 255) / 256, 256>>>(bufA, bufB, W1, b1);
    k_table <<<(VOCAB * VOCAB + 255) / 256, 256>>>(W2, b2);
    k_pubm  <<<(VOCAB * 32 + 255) / 256, 256>>>();

    for (int t = 0; t < N_STEPS; t++) {
        k_phaseA<<<(N_POS + 255) / 256, 256>>>(t, k2a[t], k2b[t]);
        k_phaseB<<<512, 256>>>(t, k1a[t], k1b[t], k2a[t], k2b[t]);
    }

    k_emit<<<(N_POS + 255) / 256, 256>>>((float*)d_out);
}